// round 13
// baseline (speedup 1.0000x reference)
#include <cuda_runtime.h>
#include <math.h>

#define BB 4
#define CCH 64
#define HH 128
#define PH 136
#define NPIX (BB*HH*HH)          // 65536
#define NROW (BB*PH*PH)          // 73984
#define NOFF (NPIX*12)           // 786432
#define NCG 8                    // channel groups in k_conv (8 ch each)

typedef unsigned long long u64;

__device__ __forceinline__ u64 pack2(float lo, float hi) {
    u64 r; asm("mov.b64 %0,{%1,%2};" : "=l"(r) : "f"(lo), "f"(hi)); return r;
}
__device__ __forceinline__ void unpack2(u64 v, float& lo, float& hi) {
    asm("mov.b64 {%0,%1},%2;" : "=f"(lo), "=f"(hi) : "l"(v));
}
__device__ __forceinline__ void ffma2(u64& d, u64 a, u64 b) {
    asm("fma.rn.f32x2 %0,%1,%2,%0;" : "+l"(d) : "l"(a), "l"(b));
}

// ---------------- scratch (static device allocations) ----------------
__device__ float  g_fp[NROW*CCH];          // padded f, NHWC  (18.9 MB)
__device__ float  g_part[NCG*NOFF];        // conv partials (8 channel groups, 25 MB)
__device__ float  g_off[NOFF];             // combined offset conv, pixel-major [pix][12]
__device__ float  g_wTd[18*64*128];        // weights repacked+duplicated [slice][c][o*2]
__device__ double g_sum[12];
__device__ double g_sumsq[12];
__device__ float  g_scale[12];
__device__ float  g_shift[12];

__constant__ int c_used[12] = {1,2,3,5,6,7,10,11,12,14,15,16};

// ---------------- K0: zero stats ----------------
__global__ void k_zero() {
    int t = threadIdx.x;
    if (t < 12) { g_sum[t] = 0.0; g_sumsq[t] = 0.0; }
}

// ---------------- K1: pad + NCHW->NHWC transpose ----------------
__global__ void __launch_bounds__(256) k_pad(const float* __restrict__ f) {
    int rb = blockIdx.x;                 // 0 .. B*136-1
    int b = rb / PH, y = rb - b * PH;
    size_t base = (size_t)rb * PH * CCH;
    int tid = threadIdx.x;
    if (y < 4 || y >= 132) {
        for (int idx = tid; idx < PH*CCH; idx += 256) g_fp[base + idx] = 0.f;
        return;
    }
    __shared__ float s[64*137];
    const float* fr = f + ((size_t)b * 64) * 16384 + (size_t)(y - 4) * 128;
    for (int idx = tid; idx < 64*128; idx += 256) {
        int c = idx >> 7, xi = idx & 127;
        s[c*137 + xi] = fr[(size_t)c * 16384 + xi];
    }
    __syncthreads();
    for (int idx = tid; idx < PH*CCH; idx += 256) {
        int x = idx >> 6, c = idx & 63;
        g_fp[base + idx] = (x >= 4 && x < 132) ? s[c*137 + (x - 4)] : 0.f;
    }
}

// ---------------- K2: repack conv weights -> [slice 18][c 64][o 64 x2 dup] ----------------
__global__ void k_wrep(const float* __restrict__ wx, const float* __restrict__ wy) {
    int g = blockIdx.x * 256 + threadIdx.x;       // 18*8192 = 147456
    if (g >= 18*8192) return;
    int s = g >> 13; int r = g & 8191; int c = r >> 7; int od = r & 127; int o = od >> 1;
    g_wTd[g] = (s < 9) ? wx[(o*64 + c)*9 + s] : wy[(o*64 + c)*9 + (s - 9)];
}

// ---------------- K3: offset conv, f32x2 packed ----------------
// tile 64 cols x 32 rows; 256 thr = 16 tx (x4 cols) x 16 ty (x2 rows)
// grid (2 xtile, 4 ytile, b*8+cg), 8 channels per group -> 256 blocks
__global__ void __launch_bounds__(256, 1) k_conv(const float* __restrict__ f,
                                                 const float* __restrict__ ow) {
    int bz = blockIdx.z; int b = bz >> 3; int cg = bz & 7;
    int x0 = blockIdx.x * 64, y0 = blockIdx.y * 32;
    __shared__ __align__(16) float s_in[40*73];
    __shared__ __align__(16) float s_wd[81*24];   // [t][m*2 dup]
    int tid = threadIdx.x;
    int tx = tid & 15, ty = tid >> 4;
    int rx = tx * 4, ry = ty * 2;

    u64 acc[12][4];
#pragma unroll
    for (int m = 0; m < 12; m++)
#pragma unroll
        for (int p = 0; p < 4; p++) acc[m][p] = 0ull;   // (0.f,0.f)

#pragma unroll 1
    for (int c0 = 0; c0 < 8; c0++) {
        int c = cg * 8 + c0;
        const float* fc = f + (size_t)(b*64 + c) * 16384;
        // stage input 40x72 window (rows y0-4..y0+35, cols x0-4..x0+67)
        for (int idx = tid; idx < 40*72; idx += 256) {
            int r = idx / 72, col = idx - r*72;
            int gy = y0 - 4 + r, gx = x0 - 4 + col;
            s_in[r*73 + col] = (gy >= 0 && gy < 128 && gx >= 0 && gx < 128)
                               ? fc[gy*128 + gx] : 0.f;
        }
        // stage duplicated weights
        for (int idx = tid; idx < 972; idx += 256) {
            int t = idx / 12, m = idx - t*12;
            float w = ow[(size_t)(c_used[m]*64 + c) * 81 + t];
            s_wd[t*24 + 2*m] = w; s_wd[t*24 + 2*m + 1] = w;
        }
        __syncthreads();

        float rw[2][12];
#pragma unroll
        for (int u = 0; u < 12; u++) rw[0][u] = s_in[ry*73 + rx + u];
#pragma unroll
        for (int ky = 0; ky < 9; ky++) {
            const int sh = (ky + 1) & 1;   // slot for row ry+ky+1 (loaded now)
            const int sl = ky & 1;         // slot holding row ry+ky
#pragma unroll
            for (int u = 0; u < 12; u++) rw[sh][u] = s_in[(ry + ky + 1)*73 + rx + u];
#pragma unroll
            for (int kx = 0; kx < 9; kx++) {
                u64 bp[4];
#pragma unroll
                for (int p = 0; p < 4; p++) bp[p] = pack2(rw[sl][kx + p], rw[sh][kx + p]);
                int t = ky*9 + kx;
#pragma unroll
                for (int m = 0; m < 12; m++) {
                    u64 a = *(const u64*)&s_wd[t*24 + 2*m];   // broadcast dup pair
#pragma unroll
                    for (int p = 0; p < 4; p++) ffma2(acc[m][p], a, bp[p]);
                }
            }
        }
        __syncthreads();
    }

    // store partials: lanes of acc = (row ry, row ry+1)
    float* dst = g_part + (size_t)cg * NOFF;
#pragma unroll
    for (int p = 0; p < 4; p++) {
        float vlo[12], vhi[12];
#pragma unroll
        for (int m = 0; m < 12; m++) unpack2(acc[m][p], vlo[m], vhi[m]);
        int pxa = x0 + rx + p;
        int pixlo = (b*128 + y0 + ry) * 128 + pxa;
        int pixhi = pixlo + 128;
#pragma unroll
        for (int q = 0; q < 3; q++) {
            *(float4*)&dst[(size_t)pixlo*12 + q*4] =
                make_float4(vlo[q*4], vlo[q*4+1], vlo[q*4+2], vlo[q*4+3]);
            *(float4*)&dst[(size_t)pixhi*12 + q*4] =
                make_float4(vhi[q*4], vhi[q*4+1], vhi[q*4+2], vhi[q*4+3]);
        }
    }
}

// ---------------- K4: combine partials + fp64 stats ----------------
__global__ void __launch_bounds__(256) k_comb() {
    int pix = blockIdx.x * 256 + threadIdx.x;     // 256 blocks
    float v[12];
#pragma unroll
    for (int m = 0; m < 12; m++) {
        float a = 0.f;
#pragma unroll
        for (int g = 0; g < NCG; g++) a += g_part[(size_t)g*NOFF + (size_t)pix*12 + m];
        v[m] = a;
        g_off[(size_t)pix*12 + m] = a;
    }
    __shared__ double ss[8][12], sq[8][12];
    int lane = threadIdx.x & 31, w = threadIdx.x >> 5;
#pragma unroll
    for (int m = 0; m < 12; m++) {
        double dv = (double)v[m];
        double dq = (double)v[m] * (double)v[m];
        for (int o = 16; o > 0; o >>= 1) {
            dv += __shfl_down_sync(0xffffffff, dv, o);
            dq += __shfl_down_sync(0xffffffff, dq, o);
        }
        if (lane == 0) { ss[w][m] = dv; sq[w][m] = dq; }
    }
    __syncthreads();
    if (threadIdx.x < 12) {
        double a = 0, q = 0;
        for (int w2 = 0; w2 < 8; w2++) { a += ss[w2][threadIdx.x]; q += sq[w2][threadIdx.x]; }
        atomicAdd(&g_sum[threadIdx.x], a);
        atomicAdd(&g_sumsq[threadIdx.x], q);
    }
}

// ---------------- K5: BN finalize ----------------
__global__ void k_final(const float* __restrict__ gamma, const float* __restrict__ beta) {
    int t = threadIdx.x;
    if (t >= 12) return;
    double mean = g_sum[t] / 65536.0;
    double var  = g_sumsq[t] / 65536.0 - mean * mean;
    double sc   = (double)gamma[c_used[t]] / sqrt(var + 1e-5);
    g_scale[t] = (float)sc;
    g_shift[t] = (float)((double)beta[c_used[t]] - mean * sc);
}

// ---------------- K6: main fused gather + GEMM, f32x2 packed ----------------
// block = 128 pixels (one b, one row i) x 64 outputs; 256 thr
// thread: pg = tid&15 (8 px), og = tid>>4 (4 outs); grid (128 i, 4 b)
// dynamic smem: s_idx int[18*128] | sWd float[64*128 dup] | sV float[64*128]
#define SM_IDX_BYTES (18*128*4)
#define SM_W_BYTES   (64*128*4)
#define SM_V_BYTES   (64*128*4)
#define SM_TOTAL     (SM_IDX_BYTES + SM_W_BYTES + SM_V_BYTES)

__global__ void __launch_bounds__(256, 2) k_main(const float* __restrict__ bx,
                                                 const float* __restrict__ by,
                                                 float* __restrict__ out) {
    extern __shared__ __align__(16) unsigned char smem_raw[];
    int*   s_idx = (int*)smem_raw;
    float* sWd   = (float*)(smem_raw + SM_IDX_BYTES);
    float* sV    = (float*)(smem_raw + SM_IDX_BYTES + SM_W_BYTES);
    int tid = threadIdx.x;
    int i = blockIdx.x, b = blockIdx.y;

    if (tid < 128) {
        int j = tid;
        const float* op = g_off + (size_t)(((b*128 + i)*128 + j)) * 12;
        float t[12];
#pragma unroll
        for (int m = 0; m < 12; m++) t[m] = tanhf(op[m] * g_scale[m] + g_shift[m]);
        float cz[9], cw[9];
        cz[0] = 0.f; cz[1] = t[0]; cz[2] = t[0] + t[1]; cz[3] = cz[2] + t[2];
        cz[7] = t[5]; cz[6] = t[5] + t[4]; cz[5] = cz[6] + t[3];
        cz[4] = (cz[3] + cz[5]) * 0.5f; cz[8] = 0.f;
        cw[0] = 0.f; cw[1] = t[6]; cw[2] = t[6] + t[7]; cw[3] = cw[2] + t[8];
        cw[7] = t[11]; cw[6] = t[11] + t[10]; cw[5] = cw[6] + t[9];
        cw[4] = (cw[3] + cw[5]) * 0.5f; cw[8] = 0.f;
#pragma unroll
        for (int k = 0; k < 9; k++) {
            float y2 = (float)(i + 8 - k) + cz[k];
            float x2 = (float)(j + k)     + cz[k];
            int idx2 = b*16384 + (int)floorf(y2) * 136 + (int)floorf(x2);
            if (idx2 < 0) idx2 += NROW;
            idx2 = idx2 < 0 ? 0 : (idx2 > NROW-1 ? NROW-1 : idx2);
            s_idx[k*128 + j] = idx2;

            float y3 = (float)(i + k) + cw[k];
            float x3 = (float)(j + k) - cw[k];
            int idx3 = b*16384 + (int)floorf(y3) * 136 + (int)floorf(x3);
            if (idx3 < 0) idx3 += NROW;
            idx3 = idx3 < 0 ? 0 : (idx3 > NROW-1 ? NROW-1 : idx3);
            s_idx[(9 + k)*128 + j] = idx3;
        }
    }

    u64 acc[4][4];   // [oi][pixel-pair]
#pragma unroll
    for (int a = 0; a < 4; a++)
#pragma unroll
        for (int p = 0; p < 4; p++) acc[a][p] = 0ull;

    int pg = tid & 15, og = tid >> 4;
    __syncthreads();

#pragma unroll 1
    for (int s = 0; s < 18; s++) {
        // stage duplicated weights (32 KB)
        const float4* wsrc = (const float4*)(g_wTd + (size_t)s * 8192);
        float4* wdst = (float4*)sWd;
#pragma unroll
        for (int u = 0; u < 8; u++) wdst[tid + u*256] = wsrc[tid + u*256];
        // gather V: thread (p = tid&127, half = tid>>7) copies 32 channels of pixel p
        int p = tid & 127, half = tid >> 7;
        const float4* vsrc = (const float4*)(g_fp + (size_t)s_idx[s*128 + p] * 64 + half*32);
#pragma unroll
        for (int u = 0; u < 8; u++) {
            float4 vv = vsrc[u];
            int cb = half*32 + u*4;
            sV[(cb+0)*128 + p] = vv.x;
            sV[(cb+1)*128 + p] = vv.y;
            sV[(cb+2)*128 + p] = vv.z;
            sV[(cb+3)*128 + p] = vv.w;
        }
        __syncthreads();
#pragma unroll 4
        for (int cc = 0; cc < 64; cc++) {
            ulonglong2 va = *(const ulonglong2*)&sV[cc*128 + pg*8];
            ulonglong2 vb = *(const ulonglong2*)&sV[cc*128 + pg*8 + 4];
            ulonglong2 wa = *(const ulonglong2*)&sWd[cc*128 + og*8];
            ulonglong2 wb = *(const ulonglong2*)&sWd[cc*128 + og*8 + 4];
            ffma2(acc[0][0], wa.x, va.x); ffma2(acc[0][1], wa.x, va.y);
            ffma2(acc[0][2], wa.x, vb.x); ffma2(acc[0][3], wa.x, vb.y);
            ffma2(acc[1][0], wa.y, va.x); ffma2(acc[1][1], wa.y, va.y);
            ffma2(acc[1][2], wa.y, vb.x); ffma2(acc[1][3], wa.y, vb.y);
            ffma2(acc[2][0], wb.x, va.x); ffma2(acc[2][1], wb.x, va.y);
            ffma2(acc[2][2], wb.x, vb.x); ffma2(acc[2][3], wb.x, vb.y);
            ffma2(acc[3][0], wb.y, va.x); ffma2(acc[3][1], wb.y, va.y);
            ffma2(acc[3][2], wb.y, vb.x); ffma2(acc[3][3], wb.y, vb.y);
        }
        __syncthreads();
    }

#pragma unroll
    for (int oi = 0; oi < 4; oi++) {
        int o = og*4 + oi;
        float bias = bx[o] + by[o];
        float r[8];
        unpack2(acc[oi][0], r[0], r[1]);
        unpack2(acc[oi][1], r[2], r[3]);
        unpack2(acc[oi][2], r[4], r[5]);
        unpack2(acc[oi][3], r[6], r[7]);
#pragma unroll
        for (int u = 0; u < 8; u++) r[u] += bias;
        size_t obase = ((size_t)(b*64 + o) * 128 + i) * 128 + pg*8;
        *(float4*)&out[obase]     = make_float4(r[0], r[1], r[2], r[3]);
        *(float4*)&out[obase + 4] = make_float4(r[4], r[5], r[6], r[7]);
    }
}

// ---------------- launch ----------------
extern "C" void kernel_launch(void* const* d_in, const int* in_sizes, int n_in,
                              void* d_out, int out_size) {
    const float* f     = (const float*)d_in[0];
    const float* ow    = (const float*)d_in[1];
    // d_in[2] offset_b: cancels exactly inside BatchNorm -> unused
    const float* gamma = (const float*)d_in[3];
    const float* beta  = (const float*)d_in[4];
    const float* wx    = (const float*)d_in[5];
    const float* bx    = (const float*)d_in[6];
    const float* wy    = (const float*)d_in[7];
    const float* by    = (const float*)d_in[8];
    float* out = (float*)d_out;

    cudaFuncSetAttribute(k_main, cudaFuncAttributeMaxDynamicSharedMemorySize, SM_TOTAL);

    k_zero<<<1, 32>>>();
    k_pad<<<BB*PH, 256>>>(f);
    k_wrep<<<576, 256>>>(wx, wy);
    k_conv<<<dim3(2, 4, 32), 256>>>(f, ow);
    k_comb<<<256, 256>>>();
    k_final<<<1, 32>>>(gamma, beta);
    k_main<<<dim3(128, 4), 256, SM_TOTAL>>>(bx, by, out);
}

// round 14
// speedup vs baseline: 1.6784x; 1.6784x over previous
#include <cuda_runtime.h>
#include <math.h>

#define BB 4
#define CCH 64
#define HH 128
#define PH 136
#define NPIX (BB*HH*HH)          // 65536
#define NROW (BB*PH*PH)          // 73984
#define NOFF (NPIX*12)           // 786432
#define NCG 8                    // channel groups in k_conv (8 ch each)

typedef unsigned long long u64;

__device__ __forceinline__ void unpack2(u64 v, float& lo, float& hi) {
    asm("mov.b64 {%0,%1},%2;" : "=f"(lo), "=f"(hi) : "l"(v));
}
__device__ __forceinline__ void ffma2(u64& d, u64 a, u64 b) {
    asm("fma.rn.f32x2 %0,%1,%2,%0;" : "+l"(d) : "l"(a), "l"(b));
}

// ---------------- scratch (static device allocations) ----------------
__device__ float  g_fp[NROW*CCH];          // padded f, NHWC  (18.9 MB)
__device__ float  g_part[NCG*NOFF];        // conv partials (8 channel groups)
__device__ float  g_off[NOFF];             // combined offset conv, pixel-major [pix][12]
__device__ float  g_wT[18*64*64];          // weights repacked [slice][c][o]
__device__ double g_sum[12];
__device__ double g_sumsq[12];
__device__ float  g_scale[12];
__device__ float  g_shift[12];

__constant__ int c_used[12] = {1,2,3,5,6,7,10,11,12,14,15,16};

// ---------------- K0: zero stats ----------------
__global__ void k_zero() {
    int t = threadIdx.x;
    if (t < 12) { g_sum[t] = 0.0; g_sumsq[t] = 0.0; }
}

// ---------------- K1: pad + NCHW->NHWC transpose ----------------
__global__ void __launch_bounds__(256) k_pad(const float* __restrict__ f) {
    int rb = blockIdx.x;                 // 0 .. B*136-1
    int b = rb / PH, y = rb - b * PH;
    size_t base = (size_t)rb * PH * CCH;
    int tid = threadIdx.x;
    if (y < 4 || y >= 132) {
        for (int idx = tid; idx < PH*CCH; idx += 256) g_fp[base + idx] = 0.f;
        return;
    }
    __shared__ float s[64*137];
    const float* fr = f + ((size_t)b * 64) * 16384 + (size_t)(y - 4) * 128;
    for (int idx = tid; idx < 64*128; idx += 256) {
        int c = idx >> 7, xi = idx & 127;
        s[c*137 + xi] = fr[(size_t)c * 16384 + xi];
    }
    __syncthreads();
    for (int idx = tid; idx < PH*CCH; idx += 256) {
        int x = idx >> 6, c = idx & 63;
        g_fp[base + idx] = (x >= 4 && x < 132) ? s[c*137 + (x - 4)] : 0.f;
    }
}

// ---------------- K2: repack conv weights -> [slice 18][c 64][o 64] ----------------
__global__ void k_wrep(const float* __restrict__ wx, const float* __restrict__ wy) {
    int g = blockIdx.x * 256 + threadIdx.x;       // 18*4096 = 73728
    if (g >= 18*4096) return;
    int s = g >> 12; int r = g & 4095; int c = r >> 6; int o = r & 63;
    g_wT[g] = (s < 9) ? wx[(o*64 + c)*9 + s] : wy[(o*64 + c)*9 + (s - 9)];
}

// ---------------- K3: offset conv, f32x2 packed, shifted-copy (no MOV packing) ----------------
// tile 64 cols x 32 rows; 256 thr = 8 tx (x8 cols = 4 col-pairs) x 32 ty (1 row)
// grid (2 xtile, 4 ytile, b*8+cg); 8 channels per group -> 256 blocks
#define IN_STRIDE 74
__global__ void __launch_bounds__(256, 1) k_conv(const float* __restrict__ f,
                                                 const float* __restrict__ ow) {
    int bz = blockIdx.z; int b = bz >> 3; int cg = bz & 7;
    int x0 = blockIdx.x * 64, y0 = blockIdx.y * 32;
    __shared__ __align__(16) float s_in[40*IN_STRIDE];   // window cols 0..71
    __shared__ __align__(16) float s_sh[40*IN_STRIDE];   // s_sh[r][c] = in[r][c+1]
    __shared__ __align__(16) u64   s_wd[81*12];          // duplicated (w,w) pairs [t][m]
    int tid = threadIdx.x;
    int tx = tid & 7, ty = tid >> 3;
    int rx = tx * 8;                                     // 8 px per thread, one row

    u64 acc[12][4];
#pragma unroll
    for (int m = 0; m < 12; m++)
#pragma unroll
        for (int p = 0; p < 4; p++) acc[m][p] = 0ull;

#pragma unroll 1
    for (int c0 = 0; c0 < 8; c0++) {
        int c = cg * 8 + c0;
        const float* fc = f + (size_t)(b*64 + c) * 16384;
        // stage input 40x72 window (rows y0-4..y0+35, cols x0-4..x0+67) + shifted copy
        for (int idx = tid; idx < 40*72; idx += 256) {
            int r = idx / 72, col = idx - r*72;
            int gy = y0 - 4 + r, gx = x0 - 4 + col;
            float v = (gy >= 0 && gy < 128 && gx >= 0 && gx < 128)
                      ? fc[gy*128 + gx] : 0.f;
            s_in[r*IN_STRIDE + col] = v;
            if (col > 0) s_sh[r*IN_STRIDE + col - 1] = v;
        }
        // stage duplicated weight pairs
        for (int idx = tid; idx < 972; idx += 256) {
            int t = idx / 12, m = idx - t*12;
            float w = ow[(size_t)(c_used[m]*64 + c) * 81 + t];
            float2 d = make_float2(w, w);
            s_wd[t*12 + m] = *(const u64*)&d;
        }
        __syncthreads();

#pragma unroll
        for (int ky = 0; ky < 9; ky++) {
            const float* row0 = &s_in[(ty + ky) * IN_STRIDE + rx];
            const float* row1 = &s_sh[(ty + ky) * IN_STRIDE + rx];
#pragma unroll
            for (int kx = 0; kx < 9; kx++) {
                u64 bp[4];
                if ((kx & 1) == 0) {
#pragma unroll
                    for (int p = 0; p < 4; p++) bp[p] = *(const u64*)&row0[kx + 2*p];
                } else {
#pragma unroll
                    for (int p = 0; p < 4; p++) bp[p] = *(const u64*)&row1[kx - 1 + 2*p];
                }
                const u64* wrow = &s_wd[(ky*9 + kx) * 12];
#pragma unroll
                for (int m = 0; m < 12; m++) {
                    u64 a = wrow[m];                     // broadcast LDS.64
                    ffma2(acc[m][0], a, bp[0]);
                    ffma2(acc[m][1], a, bp[1]);
                    ffma2(acc[m][2], a, bp[2]);
                    ffma2(acc[m][3], a, bp[3]);
                }
            }
        }
        __syncthreads();
    }

    // store partials: acc[m][p] = (col rx+2p, col rx+2p+1) of row y0+ty
    float* dst = g_part + (size_t)cg * NOFF;
#pragma unroll
    for (int p = 0; p < 4; p++) {
        float vlo[12], vhi[12];
#pragma unroll
        for (int m = 0; m < 12; m++) unpack2(acc[m][p], vlo[m], vhi[m]);
        int pixlo = (b*128 + y0 + ty) * 128 + x0 + rx + 2*p;
        int pixhi = pixlo + 1;
#pragma unroll
        for (int q = 0; q < 3; q++) {
            *(float4*)&dst[(size_t)pixlo*12 + q*4] =
                make_float4(vlo[q*4], vlo[q*4+1], vlo[q*4+2], vlo[q*4+3]);
            *(float4*)&dst[(size_t)pixhi*12 + q*4] =
                make_float4(vhi[q*4], vhi[q*4+1], vhi[q*4+2], vhi[q*4+3]);
        }
    }
}

// ---------------- K4: combine partials + fp64 stats ----------------
__global__ void __launch_bounds__(256) k_comb() {
    int pix = blockIdx.x * 256 + threadIdx.x;     // 256 blocks
    float v[12];
#pragma unroll
    for (int m = 0; m < 12; m++) {
        float a = 0.f;
#pragma unroll
        for (int g = 0; g < NCG; g++) a += g_part[(size_t)g*NOFF + (size_t)pix*12 + m];
        v[m] = a;
        g_off[(size_t)pix*12 + m] = a;
    }
    __shared__ double ss[8][12], sq[8][12];
    int lane = threadIdx.x & 31, w = threadIdx.x >> 5;
#pragma unroll
    for (int m = 0; m < 12; m++) {
        double dv = (double)v[m];
        double dq = (double)v[m] * (double)v[m];
        for (int o = 16; o > 0; o >>= 1) {
            dv += __shfl_down_sync(0xffffffff, dv, o);
            dq += __shfl_down_sync(0xffffffff, dq, o);
        }
        if (lane == 0) { ss[w][m] = dv; sq[w][m] = dq; }
    }
    __syncthreads();
    if (threadIdx.x < 12) {
        double a = 0, q = 0;
        for (int w2 = 0; w2 < 8; w2++) { a += ss[w2][threadIdx.x]; q += sq[w2][threadIdx.x]; }
        atomicAdd(&g_sum[threadIdx.x], a);
        atomicAdd(&g_sumsq[threadIdx.x], q);
    }
}

// ---------------- K5: BN finalize ----------------
__global__ void k_final(const float* __restrict__ gamma, const float* __restrict__ beta) {
    int t = threadIdx.x;
    if (t >= 12) return;
    double mean = g_sum[t] / 65536.0;
    double var  = g_sumsq[t] / 65536.0 - mean * mean;
    double sc   = (double)gamma[c_used[t]] / sqrt(var + 1e-5);
    g_scale[t] = (float)sc;
    g_shift[t] = (float)((double)beta[c_used[t]] - mean * sc);
}

// ---------------- K6: main fused gather + GEMM (R3 version, known-good) ----------------
// block = 64 pixels (one b, one row i, half-row jt) x 64 outputs
// grid (2 jt, 128 i, 4 b) = 1024 blocks, 256 threads, 4o x 4px register tile
__global__ void __launch_bounds__(256) k_main(const float* __restrict__ bx,
                                              const float* __restrict__ by,
                                              float* __restrict__ out) {
    __shared__ int   s_idx[18][64];
    __shared__ float sW[4096];   // [c][o] for current slice
    __shared__ float sV[4096];   // [c][p] gathered values
    int tid = threadIdx.x;
    int b = blockIdx.z, i = blockIdx.y, jt = blockIdx.x;

    if (tid < 64) {
        int j = jt*64 + tid;
        const float* op = g_off + (size_t)(((b*128 + i)*128 + j)) * 12;
        float t[12];
#pragma unroll
        for (int m = 0; m < 12; m++) t[m] = tanhf(op[m] * g_scale[m] + g_shift[m]);
        float cz[9], cw[9];
        cz[0] = 0.f; cz[1] = t[0]; cz[2] = t[0] + t[1]; cz[3] = cz[2] + t[2];
        cz[7] = t[5]; cz[6] = t[5] + t[4]; cz[5] = cz[6] + t[3];
        cz[4] = (cz[3] + cz[5]) * 0.5f; cz[8] = 0.f;
        cw[0] = 0.f; cw[1] = t[6]; cw[2] = t[6] + t[7]; cw[3] = cw[2] + t[8];
        cw[7] = t[11]; cw[6] = t[11] + t[10]; cw[5] = cw[6] + t[9];
        cw[4] = (cw[3] + cw[5]) * 0.5f; cw[8] = 0.f;
#pragma unroll
        for (int k = 0; k < 9; k++) {
            // replicate reference fp32 association: (int const) + cum, then floor
            float y2 = (float)(i + 8 - k) + cz[k];
            float x2 = (float)(j + k)     + cz[k];
            int idx2 = b*16384 + (int)floorf(y2) * 136 + (int)floorf(x2);
            if (idx2 < 0) idx2 += NROW;
            idx2 = idx2 < 0 ? 0 : (idx2 > NROW-1 ? NROW-1 : idx2);
            s_idx[k][tid] = idx2;

            float y3 = (float)(i + k) + cw[k];
            float x3 = (float)(j + k) - cw[k];
            int idx3 = b*16384 + (int)floorf(y3) * 136 + (int)floorf(x3);
            if (idx3 < 0) idx3 += NROW;
            idx3 = idx3 < 0 ? 0 : (idx3 > NROW-1 ? NROW-1 : idx3);
            s_idx[9 + k][tid] = idx3;
        }
    }

    float4 acc[4];
#pragma unroll
    for (int oi = 0; oi < 4; oi++) acc[oi] = make_float4(0.f, 0.f, 0.f, 0.f);
    int txp = tid & 15, tyo = tid >> 4;
    __syncthreads();

    for (int s = 0; s < 18; s++) {
        // stage weights [c][o]
        const float4* wsrc = (const float4*)(g_wT + (size_t)s * 4096);
#pragma unroll
        for (int u = 0; u < 4; u++)
            ((float4*)sW)[tid + u*256] = wsrc[tid + u*256];
        // gather V: thread (p = tid&63, cq = tid>>6) copies 16 channels of pixel p
        int p = tid & 63, cq = tid >> 6;
        const float4* vsrc = (const float4*)(g_fp + (size_t)s_idx[s][p] * 64 + cq * 16);
#pragma unroll
        for (int u = 0; u < 4; u++) {
            float4 vv = vsrc[u];
            int cb = cq*16 + u*4;
            sV[(cb+0)*64 + p] = vv.x;
            sV[(cb+1)*64 + p] = vv.y;
            sV[(cb+2)*64 + p] = vv.z;
            sV[(cb+3)*64 + p] = vv.w;
        }
        __syncthreads();
#pragma unroll 8
        for (int cc = 0; cc < 64; cc++) {
            float4 a = *(const float4*)&sW[cc*64 + tyo*4];
            float4 v = *(const float4*)&sV[cc*64 + txp*4];
            acc[0].x += a.x*v.x; acc[0].y += a.x*v.y; acc[0].z += a.x*v.z; acc[0].w += a.x*v.w;
            acc[1].x += a.y*v.x; acc[1].y += a.y*v.y; acc[1].z += a.y*v.z; acc[1].w += a.y*v.w;
            acc[2].x += a.z*v.x; acc[2].y += a.z*v.y; acc[2].z += a.z*v.z; acc[2].w += a.z*v.w;
            acc[3].x += a.w*v.x; acc[3].y += a.w*v.y; acc[3].z += a.w*v.z; acc[3].w += a.w*v.w;
        }
        __syncthreads();
    }

#pragma unroll
    for (int oi = 0; oi < 4; oi++) {
        int o = tyo*4 + oi;
        float bias = bx[o] + by[o];
        float4 r = acc[oi];
        r.x += bias; r.y += bias; r.z += bias; r.w += bias;
        *(float4*)&out[((size_t)(b*64 + o) * 128 + i) * 128 + jt*64 + txp*4] = r;
    }
}

// ---------------- launch ----------------
extern "C" void kernel_launch(void* const* d_in, const int* in_sizes, int n_in,
                              void* d_out, int out_size) {
    const float* f     = (const float*)d_in[0];
    const float* ow    = (const float*)d_in[1];
    // d_in[2] offset_b: cancels exactly inside BatchNorm -> unused
    const float* gamma = (const float*)d_in[3];
    const float* beta  = (const float*)d_in[4];
    const float* wx    = (const float*)d_in[5];
    const float* bx    = (const float*)d_in[6];
    const float* wy    = (const float*)d_in[7];
    const float* by    = (const float*)d_in[8];
    float* out = (float*)d_out;

    k_zero<<<1, 32>>>();
    k_pad<<<BB*PH, 256>>>(f);
    k_wrep<<<288, 256>>>(wx, wy);
    k_conv<<<dim3(2, 4, 32), 256>>>(f, ow);
    k_comb<<<256, 256>>>();
    k_final<<<1, 32>>>(gamma, beta);
    k_main<<<dim3(2, 128, 4), 256>>>(bx, by, out);
}